// round 1
// baseline (speedup 1.0000x reference)
#include <cuda_runtime.h>
#include <math.h>

#define BB   128
#define DD   20
#define WW   8
#define INF_ 64
#define HID  4096
#define NE   4

// -------- scratch (no allocations allowed) --------
__device__ float g_flat[BB * INF_];
__device__ int   g_expert[BB];
__device__ int   g_counts[NE];
__device__ int   g_off[NE + 1];
__device__ int   g_order[BB];
__device__ float g_h[BB * HID];
__device__ float g_p[BB * HID];   // expert logits, then probs (softmax in place)

// ============================================================
// Kernel 1: conv1 (3x3x3, pad 1) + relu, conv2 (10x20x3x3, depth-valid)
// + relu -> flat(64), gate logits, argmax expert. One block per sample.
// conv1 computed one output-channel plane at a time to keep smem static.
// ============================================================
__global__ void __launch_bounds__(256) conv_gate_kernel(
    const float* __restrict__ input,
    const float* __restrict__ c1w, const float* __restrict__ c1b,
    const float* __restrict__ c2w, const float* __restrict__ c2b,
    const float* __restrict__ wg)
{
    const int b = blockIdx.x;
    const int t = threadIdx.x;

    __shared__ float x_s[DD * 64];      // 1280
    __shared__ float y1_s[DD * 64];     // one conv1 channel plane
    __shared__ float w1_s[270];
    __shared__ float b1_s[10];
    __shared__ float w2_s[1800];
    __shared__ float accp[4][64];
    __shared__ float flat_s[64];
    __shared__ float wg_s[INF_ * NE];
    __shared__ float logit_s[NE];

    for (int i = t; i < DD * 64; i += 256) x_s[i] = input[b * (DD * 64) + i];
    for (int i = t; i < 270; i += 256)     w1_s[i] = c1w[i];
    if (t < 10)                            b1_s[t] = c1b[t];
    for (int i = t; i < 1800; i += 256)    w2_s[i] = c2w[i];
    if (t < INF_ * NE)                     wg_s[t] = wg[t];
    if (t < 64) { accp[0][t] = 0.f; accp[1][t] = 0.f; accp[2][t] = 0.f; accp[3][t] = 0.f; }
    __syncthreads();

    for (int c = 0; c < 10; c++) {
        // conv1 plane for channel c: y1[d][h][w]
        for (int idx = t; idx < DD * 64; idx += 256) {
            int d = idx >> 6, h = (idx >> 3) & 7, w = idx & 7;
            float s = b1_s[c];
            #pragma unroll
            for (int kd = 0; kd < 3; kd++) {
                int dd = d + kd - 1;
                if ((unsigned)dd >= (unsigned)DD) continue;
                #pragma unroll
                for (int kh = 0; kh < 3; kh++) {
                    int hh = h + kh - 1;
                    if ((unsigned)hh >= 8u) continue;
                    #pragma unroll
                    for (int kw = 0; kw < 3; kw++) {
                        int ww2 = w + kw - 1;
                        if ((unsigned)ww2 >= 8u) continue;
                        s += x_s[dd * 64 + hh * 8 + ww2] * w1_s[c * 27 + kd * 9 + kh * 3 + kw];
                    }
                }
            }
            y1_s[idx] = fmaxf(s, 0.f);
        }
        __syncthreads();

        // conv2 partial accumulation over this channel; 4-way split over kd
        {
            int o = t & 63, part = t >> 6;
            int h = o >> 3, w = o & 7;
            float s = 0.f;
            for (int kd = part * 5; kd < part * 5 + 5; kd++) {
                #pragma unroll
                for (int kh = 0; kh < 3; kh++) {
                    int hh = h + kh - 1;
                    if ((unsigned)hh >= 8u) continue;
                    #pragma unroll
                    for (int kw = 0; kw < 3; kw++) {
                        int ww2 = w + kw - 1;
                        if ((unsigned)ww2 >= 8u) continue;
                        s += y1_s[kd * 64 + hh * 8 + ww2] * w2_s[(c * 20 + kd) * 9 + kh * 3 + kw];
                    }
                }
            }
            accp[part][o] += s;
        }
        __syncthreads();
    }

    if (t < 64) {
        float v = accp[0][t] + accp[1][t] + accp[2][t] + accp[3][t] + c2b[0];
        v = fmaxf(v, 0.f);
        flat_s[t] = v;
        g_flat[b * 64 + t] = v;
    }
    __syncthreads();

    if (t < NE) {
        float s = 0.f;
        #pragma unroll
        for (int i = 0; i < 64; i++) s += flat_s[i] * wg_s[i * NE + t];
        logit_s[t] = s;
    }
    __syncthreads();
    if (t == 0) {
        int best = 0; float bv = logit_s[0];
        #pragma unroll
        for (int e = 1; e < NE; e++) if (logit_s[e] > bv) { bv = logit_s[e]; best = e; }
        g_expert[b] = best;
    }
}

// ============================================================
// Kernel 2: routing (counts/offsets/order) + aux loss. Deterministic
// single-thread scan (B=128 is trivial).
// ============================================================
__global__ void route_kernel(float* __restrict__ aux_out)
{
    if (threadIdx.x != 0) return;
    int cnt[NE] = {0, 0, 0, 0};
    for (int b = 0; b < BB; b++) cnt[g_expert[b]]++;
    int off = 0;
    for (int e = 0; e < NE; e++) { g_off[e] = off; g_counts[e] = cnt[e]; off += cnt[e]; }
    g_off[NE] = off;
    int cur[NE];
    for (int e = 0; e < NE; e++) cur[e] = g_off[e];
    for (int b = 0; b < BB; b++) { int e = g_expert[b]; g_order[cur[e]++] = b; }

    // importance == load == counts (gates are exactly one-hot, weight 1.0)
    float mean = (float)BB / (float)NE;                 // 32
    float var = 0.f;
    for (int e = 0; e < NE; e++) { float d = (float)cnt[e] - mean; var += d * d; }
    var /= (float)(NE - 1);                             // ddof=1
    float cv2 = var / (mean * mean + 1e-10f);
    *aux_out = 2.f * cv2 * 1e-2f;
}

// ============================================================
// Kernel 3: h[b,n] = relu(b1[e,n] + sum_i flat[b,i] * w1[e,i,n])
// grid (HID/512, B), 256 threads
// ============================================================
__global__ void __launch_bounds__(256) hidden_kernel(
    const float* __restrict__ w1, const float* __restrict__ b1)
{
    int b = blockIdx.y;
    int n0 = blockIdx.x * 512;
    int t = threadIdx.x;
    __shared__ float f_s[INF_];
    if (t < INF_) f_s[t] = g_flat[b * INF_ + t];
    __syncthreads();
    int e = g_expert[b];
    const float* w1e = w1 + (size_t)e * INF_ * HID;
    const float* b1e = b1 + (size_t)e * HID;
    for (int n = n0 + t; n < n0 + 512; n += 256) {
        float s = b1e[n];
        #pragma unroll 16
        for (int i = 0; i < INF_; i++) s += f_s[i] * w1e[(size_t)i * HID + n];
        g_h[(size_t)b * HID + n] = fmaxf(s, 0.f);
    }
}

// ============================================================
// Kernel 4: per-expert SGEMM. For expert e with cnt samples:
// logits2[b,n] = sum_k h[b,k] * w2[e,k,n] + b2[e,n]
// Tile: M=32 (samples), N=128, K=32. 256 threads, 4x4 micro-tile.
// grid (HID/128, ceil(B/32)=4, NE); blocks beyond cnt exit early.
// ============================================================
#define MT 32
#define NT 128
#define KT 32

__global__ void __launch_bounds__(256) gemm_kernel(
    const float* __restrict__ w2, const float* __restrict__ b2)
{
    const int e = blockIdx.z;
    const int cnt = g_counts[e];
    const int m0 = blockIdx.y * MT;
    if (m0 >= cnt) return;
    const int n0 = blockIdx.x * NT;

    __shared__ float As[MT][KT];
    __shared__ float Bs[KT][NT];
    __shared__ int rows[MT];

    const int t = threadIdx.x;
    if (t < MT) {
        int m = m0 + t;
        rows[t] = (m < cnt) ? g_order[g_off[e] + m] : -1;
    }
    __syncthreads();

    const int tx = t & 31;       // 32 col-groups of 4
    const int ty = t >> 5;       // 8 row-groups of 4
    float acc[4][4];
    #pragma unroll
    for (int i = 0; i < 4; i++)
        #pragma unroll
        for (int j = 0; j < 4; j++) acc[i][j] = 0.f;

    const float* w2e = w2 + (size_t)e * HID * HID;

    for (int k0 = 0; k0 < HID; k0 += KT) {
        #pragma unroll
        for (int i = 0; i < (MT * KT) / 256; i++) {
            int idx = t + i * 256;
            int m = idx >> 5, k = idx & 31;
            int r = rows[m];
            As[m][k] = (r >= 0) ? g_h[(size_t)r * HID + k0 + k] : 0.f;
        }
        #pragma unroll
        for (int q = 0; q < (KT * NT / 4) / 256; q++) {
            int idx = t + q * 256;            // float4 units
            int kk = idx >> 5;                // / (NT/4)
            int c4 = idx & 31;
            *(float4*)&Bs[kk][c4 * 4] =
                *(const float4*)(w2e + (size_t)(k0 + kk) * HID + n0 + c4 * 4);
        }
        __syncthreads();

        #pragma unroll
        for (int kk = 0; kk < KT; kk++) {
            float a0 = As[ty * 4 + 0][kk];
            float a1 = As[ty * 4 + 1][kk];
            float a2 = As[ty * 4 + 2][kk];
            float a3 = As[ty * 4 + 3][kk];
            float4 bv = *(float4*)&Bs[kk][tx * 4];
            acc[0][0] += a0 * bv.x; acc[0][1] += a0 * bv.y; acc[0][2] += a0 * bv.z; acc[0][3] += a0 * bv.w;
            acc[1][0] += a1 * bv.x; acc[1][1] += a1 * bv.y; acc[1][2] += a1 * bv.z; acc[1][3] += a1 * bv.w;
            acc[2][0] += a2 * bv.x; acc[2][1] += a2 * bv.y; acc[2][2] += a2 * bv.z; acc[2][3] += a2 * bv.w;
            acc[3][0] += a3 * bv.x; acc[3][1] += a3 * bv.y; acc[3][2] += a3 * bv.z; acc[3][3] += a3 * bv.w;
        }
        __syncthreads();
    }

    const float* b2e = b2 + (size_t)e * HID;
    float4 bb = *(const float4*)(b2e + n0 + tx * 4);
    #pragma unroll
    for (int mi = 0; mi < 4; mi++) {
        int r = rows[ty * 4 + mi];
        if (r >= 0) {
            float4 v;
            v.x = acc[mi][0] + bb.x;
            v.y = acc[mi][1] + bb.y;
            v.z = acc[mi][2] + bb.z;
            v.w = acc[mi][3] + bb.w;
            *(float4*)&g_p[(size_t)r * HID + n0 + tx * 4] = v;
        }
    }
}

// ============================================================
// Kernel 5: row softmax over HID, in place on g_p. One block per sample.
// ============================================================
__global__ void __launch_bounds__(256) softmax_kernel()
{
    int b = blockIdx.x;
    int t = threadIdx.x;
    __shared__ float red[256];
    float* row = g_p + (size_t)b * HID;

    float m = -INFINITY;
    for (int i = t; i < HID; i += 256) m = fmaxf(m, row[i]);
    red[t] = m; __syncthreads();
    for (int s = 128; s > 0; s >>= 1) {
        if (t < s) red[t] = fmaxf(red[t], red[t + s]);
        __syncthreads();
    }
    m = red[0]; __syncthreads();

    float sum = 0.f;
    for (int i = t; i < HID; i += 256) {
        float v = expf(row[i] - m);
        row[i] = v;
        sum += v;
    }
    red[t] = sum; __syncthreads();
    for (int s = 128; s > 0; s >>= 1) {
        if (t < s) red[t] += red[t + s];
        __syncthreads();
    }
    float inv = 1.f / red[0];
    for (int i = t; i < HID; i += 256) row[i] *= inv;
}

// ============================================================
// Kernel 6: out[b,d,i] = sigmoid( sum_j y[b, i*64+j] * input[b,d,j] )
// One block per sample; y row and input rows staged in shared.
// ============================================================
__global__ void __launch_bounds__(256) transform_kernel(
    const float* __restrict__ input, float* __restrict__ out)
{
    int b = blockIdx.x;
    int t = threadIdx.x;
    __shared__ float y_s[HID];
    __shared__ float x_s[DD * 64];
    for (int i = t; i < HID; i += 256)    y_s[i] = g_p[(size_t)b * HID + i];
    for (int i = t; i < DD * 64; i += 256) x_s[i] = input[b * (DD * 64) + i];
    __syncthreads();

    for (int idx = t; idx < DD * 64; idx += 256) {
        int d = idx >> 6, i = idx & 63;
        const float* yr = y_s + i * 64;
        const float* xr = x_s + d * 64;
        float s = 0.f;
        #pragma unroll 16
        for (int j = 0; j < 64; j++) s += yr[j] * xr[j];
        out[b * (DD * 64) + idx] = 1.f / (1.f + expf(-s));
    }
}

// ============================================================
extern "C" void kernel_launch(void* const* d_in, const int* in_sizes, int n_in,
                              void* d_out, int out_size)
{
    const float* input = (const float*)d_in[0];
    const float* c1w   = (const float*)d_in[1];
    const float* c1b   = (const float*)d_in[2];
    const float* c2w   = (const float*)d_in[3];
    const float* c2b   = (const float*)d_in[4];
    const float* wg    = (const float*)d_in[5];
    const float* w1    = (const float*)d_in[6];
    const float* b1    = (const float*)d_in[7];
    const float* w2    = (const float*)d_in[8];
    const float* b2    = (const float*)d_in[9];
    float* out = (float*)d_out;

    conv_gate_kernel<<<BB, 256>>>(input, c1w, c1b, c2w, c2b, wg);
    route_kernel<<<1, 32>>>(out + (out_size - 1));          // aux_loss -> last element
    hidden_kernel<<<dim3(HID / 512, BB), 256>>>(w1, b1);
    gemm_kernel<<<dim3(HID / NT, (BB + MT - 1) / MT, NE), 256>>>(w2, b2);
    softmax_kernel<<<BB, 256>>>();
    transform_kernel<<<BB, 256>>>(input, out);
}

// round 3
// speedup vs baseline: 1.7570x; 1.7570x over previous
#include <cuda_runtime.h>
#include <math.h>
#include <stdint.h>

#define BB   128
#define DD   20
#define INF_ 64
#define HID  4096
#define NE   4

#define MT 32
#define NT 128
#define KT 32
#define KSPLIT 4
#define KC (HID / KSPLIT)   // 1024

typedef unsigned long long u64;

// -------- scratch (no allocations allowed) --------
__device__ float g_flat[BB * INF_];
__device__ int   g_expert[BB];
__device__ int   g_counts[NE];
__device__ int   g_off[NE + 1];
__device__ int   g_order[BB];
__device__ float g_h[BB * HID];
__device__ float g_p[BB * HID];                  // final probs
__device__ float g_part[KSPLIT * BB * HID];      // split-K partials (8MB)

// -------- helpers --------
__device__ __forceinline__ u64 ffma2(u64 a, u64 b, u64 c) {
    u64 d;
    asm("fma.rn.f32x2 %0,%1,%2,%3;" : "=l"(d) : "l"(a), "l"(b), "l"(c));
    return d;
}
__device__ __forceinline__ void cp16(uint32_t dst, const float* src) {
    asm volatile("cp.async.cg.shared.global [%0],[%1],16;" :: "r"(dst), "l"(src));
}
union F2 { u64 u; float2 f; };

// ============================================================
// Kernel 1: conv1 (3x3x3, pad 1) + relu, conv2 (10x20x3x3) + relu
// -> flat(64), gate logits, argmax expert. One block per sample.
// ============================================================
__global__ void __launch_bounds__(256) conv_gate_kernel(
    const float* __restrict__ input,
    const float* __restrict__ c1w, const float* __restrict__ c1b,
    const float* __restrict__ c2w, const float* __restrict__ c2b,
    const float* __restrict__ wg)
{
    const int b = blockIdx.x;
    const int t = threadIdx.x;

    __shared__ float x_s[DD * 64];
    __shared__ float y1_s[DD * 64];
    __shared__ float w1_s[270];
    __shared__ float b1_s[10];
    __shared__ float w2_s[1800];
    __shared__ float accp[4][64];
    __shared__ float flat_s[64];
    __shared__ float wg_s[INF_ * NE];
    __shared__ float logit_s[NE];

    for (int i = t; i < DD * 64; i += 256) x_s[i] = input[b * (DD * 64) + i];
    for (int i = t; i < 270; i += 256)     w1_s[i] = c1w[i];
    if (t < 10)                            b1_s[t] = c1b[t];
    for (int i = t; i < 1800; i += 256)    w2_s[i] = c2w[i];
    if (t < INF_ * NE)                     wg_s[t] = wg[t];
    if (t < 64) { accp[0][t] = 0.f; accp[1][t] = 0.f; accp[2][t] = 0.f; accp[3][t] = 0.f; }
    __syncthreads();

    for (int c = 0; c < 10; c++) {
        for (int idx = t; idx < DD * 64; idx += 256) {
            int d = idx >> 6, h = (idx >> 3) & 7, w = idx & 7;
            float s = b1_s[c];
            #pragma unroll
            for (int kd = 0; kd < 3; kd++) {
                int dd = d + kd - 1;
                if ((unsigned)dd >= (unsigned)DD) continue;
                #pragma unroll
                for (int kh = 0; kh < 3; kh++) {
                    int hh = h + kh - 1;
                    if ((unsigned)hh >= 8u) continue;
                    #pragma unroll
                    for (int kw = 0; kw < 3; kw++) {
                        int ww2 = w + kw - 1;
                        if ((unsigned)ww2 >= 8u) continue;
                        s += x_s[dd * 64 + hh * 8 + ww2] * w1_s[c * 27 + kd * 9 + kh * 3 + kw];
                    }
                }
            }
            y1_s[idx] = fmaxf(s, 0.f);
        }
        __syncthreads();

        {
            int o = t & 63, part = t >> 6;
            int h = o >> 3, w = o & 7;
            float s = 0.f;
            for (int kd = part * 5; kd < part * 5 + 5; kd++) {
                #pragma unroll
                for (int kh = 0; kh < 3; kh++) {
                    int hh = h + kh - 1;
                    if ((unsigned)hh >= 8u) continue;
                    #pragma unroll
                    for (int kw = 0; kw < 3; kw++) {
                        int ww2 = w + kw - 1;
                        if ((unsigned)ww2 >= 8u) continue;
                        s += y1_s[kd * 64 + hh * 8 + ww2] * w2_s[(c * 20 + kd) * 9 + kh * 3 + kw];
                    }
                }
            }
            accp[part][o] += s;
        }
        __syncthreads();
    }

    if (t < 64) {
        float v = accp[0][t] + accp[1][t] + accp[2][t] + accp[3][t] + c2b[0];
        v = fmaxf(v, 0.f);
        flat_s[t] = v;
        g_flat[b * 64 + t] = v;
    }
    __syncthreads();

    if (t < NE) {
        float s = 0.f;
        #pragma unroll
        for (int i = 0; i < 64; i++) s += flat_s[i] * wg_s[i * NE + t];
        logit_s[t] = s;
    }
    __syncthreads();
    if (t == 0) {
        int best = 0; float bv = logit_s[0];
        #pragma unroll
        for (int e = 1; e < NE; e++) if (logit_s[e] > bv) { bv = logit_s[e]; best = e; }
        g_expert[b] = best;
    }
}

// ============================================================
// Kernel 2: routing + aux loss (single-thread deterministic scan)
// ============================================================
__global__ void route_kernel(float* __restrict__ aux_out)
{
    if (threadIdx.x != 0) return;
    int cnt[NE] = {0, 0, 0, 0};
    for (int b = 0; b < BB; b++) cnt[g_expert[b]]++;
    int off = 0;
    for (int e = 0; e < NE; e++) { g_off[e] = off; g_counts[e] = cnt[e]; off += cnt[e]; }
    g_off[NE] = off;
    int cur[NE];
    for (int e = 0; e < NE; e++) cur[e] = g_off[e];
    for (int b = 0; b < BB; b++) { int e = g_expert[b]; g_order[cur[e]++] = b; }

    float mean = (float)BB / (float)NE;
    float var = 0.f;
    for (int e = 0; e < NE; e++) { float d = (float)cnt[e] - mean; var += d * d; }
    var /= (float)(NE - 1);
    float cv2 = var / (mean * mean + 1e-10f);
    *aux_out = 2.f * cv2 * 1e-2f;
}

// ============================================================
// Kernel 3: expert-grouped hidden GEMM.
// h[r,n] = relu(b1[e,n] + sum_k flat[r,k] * w1[e,k,n]), MT=32, NT=128, K=64.
// grid (HID/NT, 1, 16): e = z&3, mtile = z>>2.
// ============================================================
__global__ void __launch_bounds__(256) hidden_kernel(
    const float* __restrict__ w1, const float* __restrict__ b1)
{
    __shared__ float As[INF_][MT];     // [k][m] 8KB
    __shared__ float Ws[INF_][NT];     // 32KB
    __shared__ int rows[MT];

    const int e  = blockIdx.z & 3;
    const int mt = blockIdx.z >> 2;
    const int cnt = g_counts[e];
    const int m0 = mt * MT;
    if (m0 >= cnt) return;
    const int n0 = blockIdx.x * NT;
    const int t = threadIdx.x;

    if (t < MT) {
        int m = m0 + t;
        rows[t] = (m < cnt) ? g_order[g_off[e] + m] : -1;
    }
    __syncthreads();

    const float* w1e = w1 + (size_t)e * INF_ * HID;

    #pragma unroll
    for (int j = 0; j < 8; j++) {                       // A: 2048 floats
        int idx = t + j * 256;
        int m = idx & 31, k = idx >> 5;
        int r = rows[m];
        As[k][m] = (r >= 0) ? g_flat[r * INF_ + k] : 0.f;
    }
    #pragma unroll
    for (int j = 0; j < 8; j++) {                       // W: 2048 float4
        int idx = t + j * 256;
        int kk = idx >> 5, c4 = idx & 31;
        *(float4*)&Ws[kk][c4 * 4] = *(const float4*)(w1e + (size_t)kk * HID + n0 + c4 * 4);
    }
    __syncthreads();

    const int tx = t & 31, ty = t >> 5;
    float acc[4][4];
    #pragma unroll
    for (int i = 0; i < 4; i++)
        #pragma unroll
        for (int j = 0; j < 4; j++) acc[i][j] = 0.f;

    #pragma unroll 8
    for (int kk = 0; kk < INF_; kk++) {
        float4 av = *(const float4*)&As[kk][ty * 4];
        float4 bv = *(const float4*)&Ws[kk][tx * 4];
        acc[0][0] += av.x * bv.x; acc[0][1] += av.x * bv.y; acc[0][2] += av.x * bv.z; acc[0][3] += av.x * bv.w;
        acc[1][0] += av.y * bv.x; acc[1][1] += av.y * bv.y; acc[1][2] += av.y * bv.z; acc[1][3] += av.y * bv.w;
        acc[2][0] += av.z * bv.x; acc[2][1] += av.z * bv.y; acc[2][2] += av.z * bv.z; acc[2][3] += av.z * bv.w;
        acc[3][0] += av.w * bv.x; acc[3][1] += av.w * bv.y; acc[3][2] += av.w * bv.z; acc[3][3] += av.w * bv.w;
    }

    float4 bb = *(const float4*)(b1 + (size_t)e * HID + n0 + tx * 4);
    #pragma unroll
    for (int mi = 0; mi < 4; mi++) {
        int r = rows[ty * 4 + mi];
        if (r >= 0) {
            float4 v;
            v.x = fmaxf(acc[mi][0] + bb.x, 0.f);
            v.y = fmaxf(acc[mi][1] + bb.y, 0.f);
            v.z = fmaxf(acc[mi][2] + bb.z, 0.f);
            v.w = fmaxf(acc[mi][3] + bb.w, 0.f);
            *(float4*)&g_h[(size_t)r * HID + n0 + tx * 4] = v;
        }
    }
}

// ============================================================
// Kernel 4: split-K per-expert SGEMM with f32x2 FMAs.
// partial[ks][r][n] = sum_{k in split ks} h[r,k] * w2[e,k,n]
// MT=32, NT=128, KT=32, KSPLIT=4. cp.async double-buffered B,
// register-prefetched A stored DUPLICATED ((a,a) pairs) in smem so
// every f32x2 operand comes straight from LDS.128 (no pack MOVs).
// grid (HID/NT=32, KSPLIT=4, 16): e = z&3, mtile = z>>2.
// ============================================================
__global__ void __launch_bounds__(256, 4) gemm_kernel(const float* __restrict__ w2)
{
    __shared__ float Bs[2][KT][NT];      // 32KB (double buffered)
    __shared__ float Ad[KT][2 * MT];     // 8KB, duplicated A ((a,a) pairs)
    __shared__ int rows[MT];

    const int e  = blockIdx.z & 3;
    const int mt = blockIdx.z >> 2;
    const int cnt = g_counts[e];
    const int m0 = mt * MT;
    if (m0 >= cnt) return;
    const int n0 = blockIdx.x * NT;
    const int kbase = blockIdx.y * KC;
    const int ks = blockIdx.y;
    const int t = threadIdx.x;

    if (t < MT) {
        int m = m0 + t;
        rows[t] = (m < cnt) ? g_order[g_off[e] + m] : -1;
    }
    __syncthreads();

    const float* w2e = w2 + (size_t)e * HID * HID;

    // A loader mapping: m = t&31, kq = (t>>5)*4  (float4 along k)
    const int am = t & 31;
    const int akq = (t >> 5) * 4;
    const int arow = rows[am];
    const float* asrc = (arow >= 0) ? (g_h + (size_t)arow * HID) : g_h;

    // B loader mapping (per q): idx = t + q*256; kk = idx>>5; c4 = idx&31
    uint32_t bsm[2];
    bsm[0] = (uint32_t)__cvta_generic_to_shared(&Bs[0][0][0]);
    bsm[1] = (uint32_t)__cvta_generic_to_shared(&Bs[1][0][0]);

    // ---- prologue: A chunk0 -> Ad ; B chunk0 -> Bs[0] (async) ----
    float4 pa = make_float4(0.f, 0.f, 0.f, 0.f);
    if (arow >= 0) pa = *(const float4*)(asrc + kbase + akq);
    *(float2*)&Ad[akq + 0][2 * am] = make_float2(pa.x, pa.x);
    *(float2*)&Ad[akq + 1][2 * am] = make_float2(pa.y, pa.y);
    *(float2*)&Ad[akq + 2][2 * am] = make_float2(pa.z, pa.z);
    *(float2*)&Ad[akq + 3][2 * am] = make_float2(pa.w, pa.w);

    {
        #pragma unroll
        for (int q = 0; q < 4; q++) {
            int idx = t + q * 256;
            int kk = idx >> 5, c4 = idx & 31;
            cp16(bsm[0] + (uint32_t)(kk * NT + c4 * 4) * 4u,
                 w2e + (size_t)(kbase + kk) * HID + n0 + c4 * 4);
        }
        asm volatile("cp.async.commit_group;");
    }

    const int tx = t & 31, ty = t >> 5;
    u64 acc[4][2];
    #pragma unroll
    for (int i = 0; i < 4; i++) { acc[i][0] = 0ULL; acc[i][1] = 0ULL; }

    const int nk = KC / KT;   // 32
    for (int i = 0; i < nk; i++) {
        const int cur = i & 1;
        if (i + 1 < nk) {
            // issue next B chunk + prefetch next A chunk into regs
            const int knext = kbase + (i + 1) * KT;
            #pragma unroll
            for (int q = 0; q < 4; q++) {
                int idx = t + q * 256;
                int kk = idx >> 5, c4 = idx & 31;
                cp16(bsm[cur ^ 1] + (uint32_t)(kk * NT + c4 * 4) * 4u,
                     w2e + (size_t)(knext + kk) * HID + n0 + c4 * 4);
            }
            asm volatile("cp.async.commit_group;");
            if (arow >= 0) pa = *(const float4*)(asrc + knext + akq);
            asm volatile("cp.async.wait_group 1;");
        } else {
            asm volatile("cp.async.wait_group 0;");
        }
        __syncthreads();   // Bs[cur] ready; Ad (this chunk) visible

        #pragma unroll 8
        for (int kk = 0; kk < KT; kk++) {
            ulonglong2 a0 = *(const ulonglong2*)&Ad[kk][8 * ty];       // (a0,a0),(a1,a1)
            ulonglong2 a1 = *(const ulonglong2*)&Ad[kk][8 * ty + 4];   // (a2,a2),(a3,a3)
            ulonglong2 bq = *(const ulonglong2*)&Bs[cur][kk][4 * tx];  // (b0,b1),(b2,b3)
            acc[0][0] = ffma2(a0.x, bq.x, acc[0][0]);
            acc[0][1] = ffma2(a0.x, bq.y, acc[0][1]);
            acc[1][0] = ffma2(a0.y, bq.x, acc[1][0]);
            acc[1][1] = ffma2(a0.y, bq.y, acc[1][1]);
            acc[2][0] = ffma2(a1.x, bq.x, acc[2][0]);
            acc[2][1] = ffma2(a1.x, bq.y, acc[2][1]);
            acc[3][0] = ffma2(a1.y, bq.x, acc[3][0]);
            acc[3][1] = ffma2(a1.y, bq.y, acc[3][1]);
        }
        __syncthreads();   // all threads done reading Ad before overwrite

        if (i + 1 < nk) {  // store prefetched A chunk (i+1) into Ad
            *(float2*)&Ad[akq + 0][2 * am] = make_float2(pa.x, pa.x);
            *(float2*)&Ad[akq + 1][2 * am] = make_float2(pa.y, pa.y);
            *(float2*)&Ad[akq + 2][2 * am] = make_float2(pa.z, pa.z);
            *(float2*)&Ad[akq + 3][2 * am] = make_float2(pa.w, pa.w);
        }
    }

    #pragma unroll
    for (int mi = 0; mi < 4; mi++) {
        int r = rows[ty * 4 + mi];
        if (r >= 0) {
            F2 c0, c1; c0.u = acc[mi][0]; c1.u = acc[mi][1];
            float4 v = make_float4(c0.f.x, c0.f.y, c1.f.x, c1.f.y);
            *(float4*)&g_part[((size_t)ks * BB + r) * HID + n0 + tx * 4] = v;
        }
    }
}

// ============================================================
// Kernel 5: sum split-K partials + bias, row softmax -> g_p.
// One block per sample; row staged in shared (16KB).
// ============================================================
__global__ void __launch_bounds__(256) softmax_kernel(const float* __restrict__ b2)
{
    const int b = blockIdx.x;
    const int t = threadIdx.x;
    __shared__ float row[HID];
    __shared__ float red[256];

    const int e = g_expert[b];
    const float* p0 = g_part + ((size_t)0 * BB + b) * HID;
    const float* p1 = g_part + ((size_t)1 * BB + b) * HID;
    const float* p2 = g_part + ((size_t)2 * BB + b) * HID;
    const float* p3 = g_part + ((size_t)3 * BB + b) * HID;
    const float* bb = b2 + (size_t)e * HID;

    float m = -INFINITY;
    for (int i = t; i < HID / 4; i += 256) {
        float4 a = ((const float4*)p0)[i];
        float4 c = ((const float4*)p1)[i];
        float4 d = ((const float4*)p2)[i];
        float4 f = ((const float4*)p3)[i];
        float4 g = ((const float4*)bb)[i];
        float4 v;
        v.x = a.x + c.x + d.x + f.x + g.x;
        v.y = a.y + c.y + d.y + f.y + g.y;
        v.z = a.z + c.z + d.z + f.z + g.z;
        v.w = a.w + c.w + d.w + f.w + g.w;
        ((float4*)row)[i] = v;
        m = fmaxf(m, fmaxf(fmaxf(v.x, v.y), fmaxf(v.z, v.w)));
    }
    red[t] = m; __syncthreads();
    for (int s = 128; s > 0; s >>= 1) {
        if (t < s) red[t] = fmaxf(red[t], red[t + s]);
        __syncthreads();
    }
    m = red[0]; __syncthreads();

    float sum = 0.f;
    for (int i = t; i < HID; i += 256) {
        float v = expf(row[i] - m);
        row[i] = v;
        sum += v;
    }
    red[t] = sum; __syncthreads();
    for (int s = 128; s > 0; s >>= 1) {
        if (t < s) red[t] += red[t + s];
        __syncthreads();
    }
    float inv = 1.f / red[0];
    for (int i = t; i < HID / 4; i += 256) {
        float4 v = ((const float4*)row)[i];
        v.x *= inv; v.y *= inv; v.z *= inv; v.w *= inv;
        ((float4*)(g_p + (size_t)b * HID))[i] = v;
    }
}

// ============================================================
// Kernel 6: out[b,d,i] = sigmoid( sum_j y[b,i*64+j] * input[b,d,j] )
// ============================================================
__global__ void __launch_bounds__(256) transform_kernel(
    const float* __restrict__ input, float* __restrict__ out)
{
    int b = blockIdx.x;
    int t = threadIdx.x;
    __shared__ float y_s[HID];
    __shared__ float x_s[DD * 64];
    for (int i = t; i < HID; i += 256)     y_s[i] = g_p[(size_t)b * HID + i];
    for (int i = t; i < DD * 64; i += 256) x_s[i] = input[b * (DD * 64) + i];
    __syncthreads();

    for (int idx = t; idx < DD * 64; idx += 256) {
        int d = idx >> 6, i = idx & 63;
        const float* yr = y_s + i * 64;
        const float* xr = x_s + d * 64;
        float s = 0.f;
        #pragma unroll 16
        for (int j = 0; j < 64; j++) s += yr[j] * xr[j];
        out[b * (DD * 64) + idx] = 1.f / (1.f + expf(-s));
    }
}

// ============================================================
extern "C" void kernel_launch(void* const* d_in, const int* in_sizes, int n_in,
                              void* d_out, int out_size)
{
    const float* input = (const float*)d_in[0];
    const float* c1w   = (const float*)d_in[1];
    const float* c1b   = (const float*)d_in[2];
    const float* c2w   = (const float*)d_in[3];
    const float* c2b   = (const float*)d_in[4];
    const float* wg    = (const float*)d_in[5];
    const float* w1    = (const float*)d_in[6];
    const float* b1    = (const float*)d_in[7];
    const float* w2    = (const float*)d_in[8];
    const float* b2    = (const float*)d_in[9];
    float* out = (float*)d_out;

    conv_gate_kernel<<<BB, 256>>>(input, c1w, c1b, c2w, c2b, wg);
    route_kernel<<<1, 32>>>(out + (out_size - 1));
    hidden_kernel<<<dim3(HID / NT, 1, 16), 256>>>(w1, b1);
    gemm_kernel<<<dim3(HID / NT, KSPLIT, 16), 256>>>(w2);
    softmax_kernel<<<BB, 256>>>(b2);
    transform_kernel<<<BB, 256>>>(input, out);
}